// round 14
// baseline (speedup 1.0000x reference)
#include <cuda_runtime.h>
#include <cuda_fp16.h>
#include <math.h>
#include <stdint.h>

// ---------------- problem constants ----------------
#define L_   4096
#define DM   2048          // D_MODEL
#define DI   4096          // D_INNER
#define NH   64            // N_HEADS
#define DH   64            // D_HEAD
#define NS   128           // D_STATE
#define CD   4352          // CONV_DIM
#define DPJ  8512          // D_IN_PROJ
#define DPJA 8704          // padded to 68*128 for GEMM tiles
#define CK   256           // CHUNK
#define NCH  32            // total chunks
#define RW   8192          // total rows = B*L

// ---------------- scratch (device globals; no allocations) ----------------
__device__ __half g_zxh[(size_t)RW * DPJA];    // in-proj output (fp16)
__device__ __half g_xBC[(size_t)RW * CD];      // conv+silu output (fp16)
__device__ float g_dt[RW * NH];
__device__ float g_dacs[RW * NH];
__device__ float g_CBt[NCH * CK * CK];
__device__ __half g_states[(size_t)NCH * NH * DH * NS];
__device__ __half g_prev[(size_t)NCH * NH * DH * NS];
__device__ __half g_y[(size_t)RW * DI];
// fp16 GEMM operands
__device__ __half g_uh[(size_t)RW * DM];
__device__ __half g_wi1[(size_t)DPJA * DM];
__device__ __half g_yh[(size_t)RW * DI];
__device__ __half g_wo1[(size_t)DM * DI];

// ================= PTX helpers =================
__device__ __forceinline__ uint32_t smem_u32(const void* p) {
    uint32_t a;
    asm("{ .reg .u64 t; cvta.to.shared.u64 t, %1; cvt.u32.u64 %0, t; }" : "=r"(a) : "l"(p));
    return a;
}
#define CPA16(dst, src) \
    asm volatile("cp.async.cg.shared.global [%0], [%1], 16;" :: "r"(dst), "l"(src) : "memory")

#define LDSM4(r, adr)                                                            \
    asm volatile("ldmatrix.sync.aligned.m8n8.x4.shared.b16 {%0,%1,%2,%3}, [%4];" \
        : "=r"((r)[0]), "=r"((r)[1]), "=r"((r)[2]), "=r"((r)[3]) : "r"(adr))

#define MMAF16(c, a, b0, b1)                                                     \
    asm volatile("mma.sync.aligned.m16n8k16.row.col.f32.f16.f16.f32 "            \
        "{%0,%1,%2,%3}, {%4,%5,%6,%7}, {%8,%9}, {%0,%1,%2,%3};"                  \
        : "+f"((c)[0]), "+f"((c)[1]), "+f"((c)[2]), "+f"((c)[3])                  \
        : "r"((a)[0]), "r"((a)[1]), "r"((a)[2]), "r"((a)[3]), "r"(b0), "r"(b1))

// ================= conversion kernels =================
__global__ __launch_bounds__(256) void cvt_h1_kernel(
    const float* __restrict__ src, __half* __restrict__ dst, long n4)
{
    long i = (long)blockIdx.x * 256 + threadIdx.x;
    if (i >= n4) return;
    float4 v = ((const float4*)src)[i];
    ((__half2*)dst)[2*i]   = __halves2half2(__float2half_rn(v.x), __float2half_rn(v.y));
    ((__half2*)dst)[2*i+1] = __halves2half2(__float2half_rn(v.z), __float2half_rn(v.w));
}

__global__ __launch_bounds__(256) void cvt_h1_pad_kernel(
    const float* __restrict__ src, __half* __restrict__ dst,
    long n4, long rows_src, long cols4)
{
    long i = (long)blockIdx.x * 256 + threadIdx.x;
    if (i >= n4) return;
    float4 v = make_float4(0.f, 0.f, 0.f, 0.f);
    if (i / cols4 < rows_src) v = ((const float4*)src)[i];
    ((__half2*)dst)[2*i]   = __halves2half2(__float2half_rn(v.x), __float2half_rn(v.y));
    ((__half2*)dst)[2*i+1] = __halves2half2(__float2half_rn(v.z), __float2half_rn(v.w));
}

// ================= fp16 1-pass NT GEMM 128x128 (GEMM1) =================
#define FSTAGES 3
#define FROWH 40
#define FTILE (128 * FROWH)
#define FSTAGE (2 * FTILE)
#define FGEMM_SMEM (FSTAGES * FSTAGE * 2)

template <bool OUTH>
__global__ __launch_bounds__(256, 2) void gemm_f16(
    const __half* __restrict__ A1, const __half* __restrict__ B1,
    void* __restrict__ Cv, int Ktot, int ldc)
{
    extern __shared__ __half fsm[];
    const int tid = threadIdx.x;
    const int wid = tid >> 5;
    const int lane = tid & 31;

    const int m0 = blockIdx.y * 128;
    const int n0 = blockIdx.x * 128;

    const int lrow = tid >> 2;
    const int lch  = (tid & 3) * 8;

    const __half* a1p = A1 + (size_t)m0 * Ktot;
    const __half* b1p = B1 + (size_t)n0 * Ktot;

    auto load_stage = [&](int s, int k0) {
        __half* st = fsm + s * FSTAGE;
#pragma unroll
        for (int q = 0; q < 2; q++) {
            int row = lrow + q * 64;
            uint32_t d = smem_u32(st + row * FROWH + lch);
            CPA16(d,             a1p + (size_t)row * Ktot + k0 + lch);
            CPA16(d + FTILE * 2, b1p + (size_t)row * Ktot + k0 + lch);
        }
        asm volatile("cp.async.commit_group;" ::: "memory");
    };

    const int wm = (wid & 1) * 64;
    const int wn = (wid >> 1) * 32;
    const int fr = lane & 15;
    const int fch = (lane >> 4) * 8;

    float acc[4][4][4];
#pragma unroll
    for (int a = 0; a < 4; a++)
#pragma unroll
        for (int b = 0; b < 4; b++)
#pragma unroll
            for (int c = 0; c < 4; c++) acc[a][b][c] = 0.f;

    const int KT = Ktot / 32;
    load_stage(0, 0);
    load_stage(1, 32);

    int cur = 0, nxt = 2;
    for (int kt = 0; kt < KT; kt++) {
        if (kt < KT - 1) {
            asm volatile("cp.async.wait_group 1;" ::: "memory");
        } else {
            asm volatile("cp.async.wait_group 0;" ::: "memory");
        }
        __syncthreads();
        if (kt + 2 < KT) load_stage(nxt, (kt + 2) * 32);

        const __half* st = fsm + cur * FSTAGE;
#pragma unroll
        for (int kk = 0; kk < 2; kk++) {
            const int kof = kk * 16;
            uint32_t af[4][4];
#pragma unroll
            for (int mb = 0; mb < 4; mb++) {
                uint32_t adr = smem_u32(st + (wm + mb * 16 + fr) * FROWH + kof + fch);
                LDSM4(af[mb], adr);
            }
            uint32_t bf[2][4];
#pragma unroll
            for (int nb2 = 0; nb2 < 2; nb2++) {
                uint32_t adr = smem_u32(st + FTILE + (wn + nb2 * 16 + fr) * FROWH + kof + fch);
                LDSM4(bf[nb2], adr);
            }
#pragma unroll
            for (int mb = 0; mb < 4; mb++)
#pragma unroll
                for (int nb = 0; nb < 4; nb++)
                    MMAF16(acc[mb][nb], af[mb], bf[nb >> 1][nb & 1], bf[nb >> 1][(nb & 1) + 2]);
        }
        cur = (cur == 2) ? 0 : cur + 1;
        nxt = (nxt == 2) ? 0 : nxt + 1;
    }

    const int er = lane >> 2;
    const int ec = (lane & 3) * 2;
#pragma unroll
    for (int mb = 0; mb < 4; mb++) {
#pragma unroll
        for (int nb = 0; nb < 4; nb++) {
            const size_t r0 = (size_t)(m0 + wm + mb * 16 + er) * ldc + n0 + wn + nb * 8 + ec;
            const size_t r1 = r0 + (size_t)8 * ldc;
            if (OUTH) {
                __half* C = (__half*)Cv;
                *(__half2*)&C[r0] = __halves2half2(__float2half_rn(acc[mb][nb][0]),
                                                   __float2half_rn(acc[mb][nb][1]));
                *(__half2*)&C[r1] = __halves2half2(__float2half_rn(acc[mb][nb][2]),
                                                   __float2half_rn(acc[mb][nb][3]));
            } else {
                float* C = (float*)Cv;
                *(float2*)&C[r0] = make_float2(acc[mb][nb][0], acc[mb][nb][1]);
                *(float2*)&C[r1] = make_float2(acc[mb][nb][2], acc[mb][nb][3]);
            }
        }
    }
}

// ================= fp16 1-pass NT GEMM 128x64 (GEMM2: wave tail), 2 CTAs/SM =================
#define NROWH 40
#define NA_TILE (128 * NROWH)
#define NB_TILE (64 * NROWH)
#define NSTAGE (NA_TILE + NB_TILE)
#define NGEMM_SMEM (3 * NSTAGE * 2)    // 46080 B

__global__ __launch_bounds__(256, 2) void gemm_f16_n64(
    const __half* __restrict__ A1, const __half* __restrict__ B1,
    float* __restrict__ C, int Ktot, int ldc)
{
    extern __shared__ __half fsm[];
    const int tid = threadIdx.x;
    const int wid = tid >> 5;
    const int lane = tid & 31;

    const int m0 = blockIdx.y * 128;
    const int n0 = blockIdx.x * 64;

    const int lrow = tid >> 2;           // 0..63
    const int lch  = (tid & 3) * 8;

    const __half* a1p = A1 + (size_t)m0 * Ktot;
    const __half* b1p = B1 + (size_t)n0 * Ktot;

    auto load_stage = [&](int s, int k0) {
        __half* st = fsm + s * NSTAGE;
#pragma unroll
        for (int q = 0; q < 2; q++) {
            int row = lrow + q * 64;
            uint32_t d = smem_u32(st + row * NROWH + lch);
            CPA16(d, a1p + (size_t)row * Ktot + k0 + lch);
        }
        {
            uint32_t d = smem_u32(st + NA_TILE + lrow * NROWH + lch);
            CPA16(d, b1p + (size_t)lrow * Ktot + k0 + lch);
        }
        asm volatile("cp.async.commit_group;" ::: "memory");
    };

    // 8 warps: 2 along M (64 rows), 4 along N (16 cols)
    const int wm = (wid & 1) * 64;
    const int wn = (wid >> 1) * 16;
    const int fr = lane & 15;
    const int fch = (lane >> 4) * 8;

    float acc[4][2][4];
#pragma unroll
    for (int a = 0; a < 4; a++)
#pragma unroll
        for (int b = 0; b < 2; b++)
#pragma unroll
            for (int c = 0; c < 4; c++) acc[a][b][c] = 0.f;

    const int KT = Ktot / 32;
    load_stage(0, 0);
    load_stage(1, 32);

    int cur = 0, nxt = 2;
    for (int kt = 0; kt < KT; kt++) {
        if (kt < KT - 1) {
            asm volatile("cp.async.wait_group 1;" ::: "memory");
        } else {
            asm volatile("cp.async.wait_group 0;" ::: "memory");
        }
        __syncthreads();
        if (kt + 2 < KT) load_stage(nxt, (kt + 2) * 32);

        const __half* st = fsm + cur * NSTAGE;
#pragma unroll
        for (int kk = 0; kk < 2; kk++) {
            const int kof = kk * 16;
            uint32_t af[4][4];
#pragma unroll
            for (int mb = 0; mb < 4; mb++) {
                uint32_t adr = smem_u32(st + (wm + mb * 16 + fr) * NROWH + kof + fch);
                LDSM4(af[mb], adr);
            }
            uint32_t bf[4];
            {
                uint32_t adr = smem_u32(st + NA_TILE + (wn + fr) * NROWH + kof + fch);
                LDSM4(bf, adr);
            }
#pragma unroll
            for (int mb = 0; mb < 4; mb++)
#pragma unroll
                for (int nb = 0; nb < 2; nb++)
                    MMAF16(acc[mb][nb], af[mb], bf[nb], bf[nb + 2]);
        }
        cur = (cur == 2) ? 0 : cur + 1;
        nxt = (nxt == 2) ? 0 : nxt + 1;
    }

    const int er = lane >> 2;
    const int ec = (lane & 3) * 2;
#pragma unroll
    for (int mb = 0; mb < 4; mb++) {
#pragma unroll
        for (int nb = 0; nb < 2; nb++) {
            float* p0 = C + (size_t)(m0 + wm + mb * 16 + er) * ldc + n0 + wn + nb * 8 + ec;
            float* p1 = p0 + 8 * ldc;
            *(float2*)p0 = make_float2(acc[mb][nb][0], acc[mb][nb][1]);
            *(float2*)p1 = make_float2(acc[mb][nb][2], acc[mb][nb][3]);
        }
    }
}

// ---------------- per-chunk CBt via fp16 MMA ----------------
#define CBT_SMEM ((128*136 + 256*136) * 2)

__global__ __launch_bounds__(256, 1) void cbt_tc()
{
    extern __shared__ __half csm[];
    __half* Bs = csm;
    __half* Cs = csm + 128 * 136;

    const int chunk = blockIdx.y, j0 = blockIdx.x * 128, base = chunk * CK;
    const int tid = threadIdx.x;

#pragma unroll
    for (int e = 0; e < 8; e++) {
        int idx = tid + e * 256;
        int r = idx >> 4, c8 = (idx & 15) * 8;
        *(uint4*)&Bs[r * 136 + c8] =
            *(const uint4*)&g_xBC[(size_t)(base + j0 + r) * CD + DI + c8];
    }
#pragma unroll
    for (int e = 0; e < 16; e++) {
        int idx = tid + e * 256;
        int r = idx >> 4, c8 = (idx & 15) * 8;
        *(uint4*)&Cs[r * 136 + c8] =
            *(const uint4*)&g_xBC[(size_t)(base + r) * CD + DI + NS + c8];
    }
    __syncthreads();

    const int wid = tid >> 5, lane = tid & 31;
    const int wm = (wid & 1) * 64;
    const int wn = (wid >> 1) * 64;
    const int fr = lane & 15, fch = (lane >> 4) * 8;

    float acc[4][8][4];
#pragma unroll
    for (int a = 0; a < 4; a++)
#pragma unroll
        for (int b = 0; b < 8; b++)
#pragma unroll
            for (int c = 0; c < 4; c++) acc[a][b][c] = 0.f;

#pragma unroll
    for (int ks = 0; ks < 8; ks++) {
        uint32_t af[4][4];
#pragma unroll
        for (int mb = 0; mb < 4; mb++)
            LDSM4(af[mb], smem_u32(Bs + (wm + mb * 16 + fr) * 136 + ks * 16 + fch));
        uint32_t bf[4][4];
#pragma unroll
        for (int nb2 = 0; nb2 < 4; nb2++)
            LDSM4(bf[nb2], smem_u32(Cs + (wn + nb2 * 16 + fr) * 136 + ks * 16 + fch));
#pragma unroll
        for (int mb = 0; mb < 4; mb++)
#pragma unroll
            for (int nb = 0; nb < 8; nb++)
                MMAF16(acc[mb][nb], af[mb], bf[nb >> 1][nb & 1], bf[nb >> 1][(nb & 1) + 2]);
    }

    float* cbt = g_CBt + (size_t)chunk * CK * CK;
    const int er = lane >> 2, ec = (lane & 3) * 2;
#pragma unroll
    for (int mb = 0; mb < 4; mb++) {
        int j = j0 + wm + mb * 16 + er;
#pragma unroll
        for (int nb = 0; nb < 8; nb++) {
            int i = wn + nb * 8 + ec;
            *(float2*)&cbt[(size_t)j * CK + i] = make_float2(acc[mb][nb][0], acc[mb][nb][1]);
            *(float2*)&cbt[(size_t)(j + 8) * CK + i] = make_float2(acc[mb][nb][2], acc[mb][nb][3]);
        }
    }
}

// ---------------- tiled causal depthwise conv (width 4) + SiLU (fp16 in/out) ----------------
#define CT_ROWS 16
__global__ __launch_bounds__(256) void conv_silu_kernel(const float* __restrict__ conv_w,
                                                        const float* __restrict__ conv_b)
{
    __shared__ float ts[CT_ROWS + 3][256];
    const int c0 = blockIdx.x * 256;
    const int r0 = blockIdx.y * CT_ROWS;
    const int tid = threadIdx.x;
    const int cc = c0 + tid;
    const int batch_start = r0 & ~(L_ - 1);

    const __half* src = g_zxh + DI + cc;
#pragma unroll
    for (int rr = 0; rr < CT_ROWS + 3; rr++) {
        int x = r0 - 3 + rr;
        ts[rr][tid] = (x >= batch_start) ? __half2float(src[(size_t)x * DPJA]) : 0.f;
    }
    __syncthreads();

    const float cw0 = conv_w[cc*4+0], cw1 = conv_w[cc*4+1];
    const float cw2 = conv_w[cc*4+2], cw3 = conv_w[cc*4+3];
    const float cb = conv_b[cc];
#pragma unroll
    for (int rr = 0; rr < CT_ROWS; rr++) {
        float acc = cb + ts[rr][tid]*cw0 + ts[rr+1][tid]*cw1
                       + ts[rr+2][tid]*cw2 + ts[rr+3][tid]*cw3;
        float s = acc / (1.0f + __expf(-acc));
        g_xBC[(size_t)(r0 + rr) * CD + cc] = __float2half_rn(s);
    }
}

// ---------------- dt softplus + within-chunk cumsum (parallel scan) ----------------
__global__ __launch_bounds__(256) void dt_cumsum_kernel(const float* __restrict__ dt_bias,
                                                        const float* __restrict__ A_log)
{
    __shared__ float wsum[8];
    const int chunk = blockIdx.x;
    const int h = blockIdx.y;
    const int i = threadIdx.x;
    const int lane = i & 31, wid = i >> 5;
    const int r = chunk * CK + i;

    float Ahd = -expf(A_log[h]);
    float x = __half2float(g_zxh[(size_t)r * DPJA + DI + CD + h]) + dt_bias[h];
    float dt = fmaxf(x, 0.f) + log1pf(expf(-fabsf(x)));
    g_dt[r*NH + h] = dt;

    float v = dt * Ahd;
#pragma unroll
    for (int o = 1; o < 32; o <<= 1) {
        float n = __shfl_up_sync(0xffffffffu, v, o);
        if (lane >= o) v += n;
    }
    if (lane == 31) wsum[wid] = v;
    __syncthreads();
    float add = 0.f;
#pragma unroll
    for (int wq = 0; wq < 8; wq++) {
        float ws = wsum[wq];
        add += (wq < wid) ? ws : 0.f;
    }
    g_dacs[r*NH + h] = v + add;
}

// ---------------- states via fp16 MMA (fp16 output) ----------------
#define ST_SMEM (1024 + 64*264*2 + 128*264*2)

__global__ __launch_bounds__(256, 2) void states_tc()
{
    extern __shared__ char sm0[];
    float* ws = (float*)sm0;
    __half* At = (__half*)(sm0 + 1024);
    __half* Bt = (__half*)(sm0 + 1024 + 64*264*2);

    const int chunk = blockIdx.x, h = blockIdx.y, base = chunk * CK;
    const int tid = threadIdx.x;

    {
        float dl = g_dacs[(base + CK - 1)*NH + h];
        float dv = g_dacs[(base + tid)*NH + h];
        ws[tid] = __expf(dl - dv) * g_dt[(base + tid)*NH + h];
    }
    __syncthreads();

#pragma unroll 4
    for (int e = 0; e < 64; e++) {
        int idx = tid + e * 256;
        int p = idx & 63, s = idx >> 6;
        float x = __half2float(g_xBC[(size_t)(base + s) * CD + h * 64 + p]);
        At[p * 264 + s] = __float2half_rn(ws[s] * x);
    }
#pragma unroll 4
    for (int e = 0; e < 128; e++) {
        int idx = tid + e * 256;
        int n = idx & 127, s = idx >> 7;
        Bt[n * 264 + s] = g_xBC[(size_t)(base + s) * CD + DI + n];
    }
    __syncthreads();

    const int wid = tid >> 5, lane = tid & 31;
    const int wm = (wid & 1) * 32;
    const int wn = (wid >> 1) * 32;
    const int fr = lane & 15, fch = (lane >> 4) * 8;

    float acc[2][4][4];
#pragma unroll
    for (int a = 0; a < 2; a++)
#pragma unroll
        for (int b = 0; b < 4; b++)
#pragma unroll
            for (int c = 0; c < 4; c++) acc[a][b][c] = 0.f;

#pragma unroll
    for (int ks = 0; ks < 16; ks++) {
        uint32_t af[2][4];
#pragma unroll
        for (int mb = 0; mb < 2; mb++)
            LDSM4(af[mb], smem_u32(At + (wm + mb * 16 + fr) * 264 + ks * 16 + fch));
        uint32_t bf[2][4];
#pragma unroll
        for (int nb2 = 0; nb2 < 2; nb2++)
            LDSM4(bf[nb2], smem_u32(Bt + (wn + nb2 * 16 + fr) * 264 + ks * 16 + fch));
#pragma unroll
        for (int mb = 0; mb < 2; mb++)
#pragma unroll
            for (int nb = 0; nb < 4; nb++)
                MMAF16(acc[mb][nb], af[mb], bf[nb >> 1][nb & 1], bf[nb >> 1][(nb & 1) + 2]);
    }

    size_t obase = (size_t)(chunk * NH + h) * DH * NS;
    const int er = lane >> 2, ec = (lane & 3) * 2;
#pragma unroll
    for (int mb = 0; mb < 2; mb++) {
        int p0 = wm + mb * 16 + er;
#pragma unroll
        for (int nb = 0; nb < 4; nb++) {
            int col = wn + nb * 8 + ec;
            *(__half2*)&g_states[obase + (size_t)p0 * NS + col] =
                __halves2half2(__float2half_rn(acc[mb][nb][0]), __float2half_rn(acc[mb][nb][1]));
            *(__half2*)&g_states[obase + (size_t)(p0 + 8) * NS + col] =
                __halves2half2(__float2half_rn(acc[mb][nb][2]), __float2half_rn(acc[mb][nb][3]));
        }
    }
}

// ---------------- inter-chunk scan (fp16 in/out, fp32 accum) ----------------
__global__ void scan_kernel()
{
    int idx = blockIdx.x * 256 + threadIdx.x;
    int h = (idx >> 13) & 63;
    int b = idx >> 19;
    float s = 0.f;
    for (int c = 0; c < 16; c++) {
        size_t off = ((size_t)(b*16 + c)*NH + h)*DH*NS + (idx & 8191);
        g_prev[off] = __float2half_rn(s);
        float dec = __expf(g_dacs[(size_t)(b*L_ + c*CK + CK - 1)*NH + h]);
        s = s * dec + __half2float(g_states[off]);
    }
}

// ---------------- y via fp16 MMA (fp16 in/out) ----------------
#define YTC_SMEM 76288

__global__ __launch_bounds__(256, 2) void y_tc(const float* __restrict__ Dp)
{
    extern __shared__ char sm1[];
    float* das  = (float*)sm1;
    float* q    = das + 256;
    float* rqd  = q + 256;
    float* ei   = rqd + 256;
    float* Sarr = ei + 256;
    float* PP   = Sarr + 8;
    __half* xT    = (__half*)(sm1 + 4608);
    __half* prevB = (__half*)(sm1 + 38400);
    __half* Mt    = (__half*)(sm1 + 55808);

    const int chunk = blockIdx.x, h = blockIdx.y, base = chunk * CK;
    const int tid = threadIdx.x;
    const int wid = tid >> 5, lane = tid & 31;

    das[tid] = g_dacs[(base + tid)*NH + h];

#pragma unroll 4
    for (int e = 0; e < 64; e++) {
        int idx = tid + e * 256;
        int p = idx & 63, s = idx >> 6;
        xT[p * 264 + s] = g_xBC[(size_t)(base + s) * CD + h * 64 + p];
    }
    {
        size_t pb = (size_t)(chunk * NH + h) * DH * NS;
#pragma unroll 4
        for (int e = 0; e < 32; e++) {
            int idx = tid + e * 256;
            int p = idx >> 7, n = idx & 127;
            prevB[p * 136 + n] = g_prev[pb + idx];
        }
    }
    __syncthreads();
    {
        int si = tid >> 5;
        float ref = das[si * 32];
        float d = das[tid];
        q[tid]   = __expf(d - ref);
        rqd[tid] = __expf(ref - d) * g_dt[(base + tid)*NH + h];
        ei[tid]  = __expf(d);
        if (tid < 8)
            Sarr[tid] = (tid == 0) ? 1.f : __expf(das[tid*32] - das[tid*32 - 32]);
    }
    __syncthreads();
    if (tid < 64) {
        int si = tid >> 3, sj = tid & 7;
        float p = 0.f;
        if (si >= sj) {
            p = 1.f;
            for (int t = sj + 1; t <= si; t++) p *= Sarr[t];
        }
        PP[tid] = p;
    }
    __syncthreads();

    const int wm = (wid >> 1) * 64;
    const int wn = (wid & 1) * 32;
    const int fr = lane & 15, fch = (lane >> 4) * 8;

    float acc[4][4][4];
#pragma unroll
    for (int a = 0; a < 4; a++)
#pragma unroll
        for (int b = 0; b < 4; b++)
#pragma unroll
            for (int c = 0; c < 4; c++) acc[a][b][c] = 0.f;

    // ---- y_diag ----
    const float* cbb = g_CBt + (size_t)chunk * CK * CK;
    for (int jt = 0; jt < 8; jt++) {
        const int j0 = jt * 32;
        {
            const int i = tid;
            const float fq = q[i] * PP[(i >> 5) * 8 + jt];
            const float* cbp = cbb + (size_t)j0 * CK + i;
            __half2* mrow = (__half2*)(Mt + i * 40);
#pragma unroll
            for (int jp = 0; jp < 16; jp++) {
                int j  = 2 * jp;
                int jj = j0 + j;
                float v0 = (jj     <= i) ? cbp[(size_t)j * CK]     * fq * rqd[jj]     : 0.f;
                float v1 = (jj + 1 <= i) ? cbp[(size_t)(j+1) * CK] * fq * rqd[jj + 1] : 0.f;
                mrow[jp] = __halves2half2(__float2half_rn(v0), __float2half_rn(v1));
            }
        }
        __syncthreads();
        if (j0 < wm + 64) {
#pragma unroll
            for (int kk = 0; kk < 2; kk++) {
                uint32_t af[4][4];
#pragma unroll
                for (int mb = 0; mb < 4; mb++)
                    LDSM4(af[mb], smem_u32(Mt + (wm + mb * 16 + fr) * 40 + kk * 16 + fch));
                uint32_t bf[2][4];
#pragma unroll
                for (int nb2 = 0; nb2 < 2; nb2++)
                    LDSM4(bf[nb2], smem_u32(xT + (wn + nb2 * 16 + fr) * 264 + j0 + kk * 16 + fch));
#pragma unroll
                for (int mb = 0; mb < 4; mb++)
#pragma unroll
                    for (int nb = 0; nb < 4; nb++)
                        MMAF16(acc[mb][nb], af[mb], bf[nb >> 1][nb & 1], bf[nb >> 1][(nb & 1) + 2]);
            }
        }
        __syncthreads();
    }

    // ---- y_off ----
    for (int nt = 0; nt < 4; nt++) {
        const int n0 = nt * 32;
        {
            const int i = tid;
            const float e = ei[i];
            const __half2* cp2 = (const __half2*)&g_xBC[(size_t)(base + i) * CD + DI + NS + n0];
            __half2* mrow = (__half2*)(Mt + i * 40);
#pragma unroll
            for (int j2 = 0; j2 < 16; j2++) {
                __half2 v = cp2[j2];
                mrow[j2] = __floats2half2_rn(e * __low2float(v), e * __high2float(v));
            }
        }
        __syncthreads();
#pragma unroll
        for (int kk = 0; kk < 2; kk++) {
            uint32_t af[4][4];
#pragma unroll
            for (int mb = 0; mb < 4; mb++)
                LDSM4(af[mb], smem_u32(Mt + (wm + mb * 16 + fr) * 40 + kk * 16 + fch));
            uint32_t bf[2][4];
#pragma unroll
            for (int nb2 = 0; nb2 < 2; nb2++)
                LDSM4(bf[nb2], smem_u32(prevB + (wn + nb2 * 16 + fr) * 136 + n0 + kk * 16 + fch));
#pragma unroll
            for (int mb = 0; mb < 4; mb++)
#pragma unroll
                for (int nb = 0; nb < 4; nb++)
                    MMAF16(acc[mb][nb], af[mb], bf[nb >> 1][nb & 1], bf[nb >> 1][(nb & 1) + 2]);
        }
        __syncthreads();
    }

    // ---- epilogue ----
    const float dph = Dp[h];
    const int er = lane >> 2, ec = (lane & 3) * 2;
#pragma unroll
    for (int mb = 0; mb < 4; mb++) {
        int i0 = wm + mb * 16 + er;
#pragma unroll
        for (int nb = 0; nb < 4; nb++) {
            int p = wn + nb * 8 + ec;
            float x00 = __half2float(xT[(size_t)p * 264 + i0]);
            float x01 = __half2float(xT[(size_t)(p + 1) * 264 + i0]);
            float x10 = __half2float(xT[(size_t)p * 264 + i0 + 8]);
            float x11 = __half2float(xT[(size_t)(p + 1) * 264 + i0 + 8]);
            *(__half2*)&g_y[(size_t)(base + i0) * DI + h * 64 + p] =
                __halves2half2(__float2half_rn(acc[mb][nb][0] + dph * x00),
                               __float2half_rn(acc[mb][nb][1] + dph * x01));
            *(__half2*)&g_y[(size_t)(base + i0 + 8) * DI + h * 64 + p] =
                __halves2half2(__float2half_rn(acc[mb][nb][2] + dph * x10),
                               __float2half_rn(acc[mb][nb][3] + dph * x11));
        }
    }
}

// ---------------- gate (silu(z)) + RMSNorm; fp16 in/out ----------------
__global__ __launch_bounds__(256) void gate_norm_kernel(const float* __restrict__ norm_w)
{
    __shared__ float buf[DI];
    __shared__ float red[8];
    int r = blockIdx.x;
    int tid = threadIdx.x;
    float ss = 0.f;
#pragma unroll
    for (int e = 0; e < 16; e++) {
        int c = tid + e*256;
        float y = __half2float(g_y[(size_t)r*DI + c]);
        float z = __half2float(g_zxh[(size_t)r*DPJA + c]);
        float g = y * (z / (1.f + __expf(-z)));
        buf[c] = g;
        ss += g*g;
    }
#pragma unroll
    for (int o = 16; o > 0; o >>= 1) ss += __shfl_xor_sync(0xffffffffu, ss, o);
    if ((tid & 31) == 0) red[tid >> 5] = ss;
    __syncthreads();
    float tot = 0.f;
#pragma unroll
    for (int q = 0; q < 8; q++) tot += red[q];
    float scale = rsqrtf(tot / (float)DI + 1e-5f);
#pragma unroll
    for (int e = 0; e < 16; e++) {
        int c = tid + e*256;
        g_yh[(size_t)r*DI + c] = __float2half_rn(buf[c] * scale * norm_w[c]);
    }
}

// ---------------- launch ----------------
extern "C" void kernel_launch(void* const* d_in, const int* in_sizes, int n_in,
                              void* d_out, int out_size)
{
    const float* u       = (const float*)d_in[0];
    const float* W_in    = (const float*)d_in[1];
    const float* conv_w  = (const float*)d_in[2];
    const float* conv_b  = (const float*)d_in[3];
    const float* dt_bias = (const float*)d_in[4];
    const float* A_log   = (const float*)d_in[5];
    const float* Dp      = (const float*)d_in[6];
    const float* norm_w  = (const float*)d_in[7];
    const float* W_out   = (const float*)d_in[8];
    float* out = (float*)d_out;

    __half *zxh, *uh, *wi1, *yh, *wo1;
    cudaGetSymbolAddress((void**)&zxh, g_zxh);
    cudaGetSymbolAddress((void**)&uh,  g_uh);
    cudaGetSymbolAddress((void**)&wi1, g_wi1);
    cudaGetSymbolAddress((void**)&yh,  g_yh);
    cudaGetSymbolAddress((void**)&wo1, g_wo1);

    cudaFuncSetAttribute(gemm_f16<true>,  cudaFuncAttributeMaxDynamicSharedMemorySize, FGEMM_SMEM);
    cudaFuncSetAttribute(gemm_f16_n64,    cudaFuncAttributeMaxDynamicSharedMemorySize, NGEMM_SMEM);
    cudaFuncSetAttribute(cbt_tc,    cudaFuncAttributeMaxDynamicSharedMemorySize, CBT_SMEM);
    cudaFuncSetAttribute(states_tc, cudaFuncAttributeMaxDynamicSharedMemorySize, ST_SMEM);
    cudaFuncSetAttribute(y_tc,      cudaFuncAttributeMaxDynamicSharedMemorySize, YTC_SMEM);

    // convert inputs for GEMM1
    {
        long n4 = (long)RW * DM / 4;
        cvt_h1_kernel<<<(int)((n4 + 255) / 256), 256>>>(u, uh, n4);
    }
    {
        long n4 = (long)DPJA * DM / 4;
        cvt_h1_pad_kernel<<<(int)((n4 + 255) / 256), 256>>>(W_in, wi1, n4, DPJ, DM/4);
    }

    // 1) in-proj (fp16 GEMM 128x128, fp16 output)
    gemm_f16<true><<<dim3(DPJA/128, RW/128), 256, FGEMM_SMEM>>>(uh, wi1, zxh, DM, DPJA);

    // 2) conv + silu
    conv_silu_kernel<<<dim3(CD/256, RW/CT_ROWS), 256>>>(conv_w, conv_b);

    // 3) dt softplus + per-chunk cumsum
    dt_cumsum_kernel<<<dim3(NCH, NH), 256>>>(dt_bias, A_log);

    // 4) per-chunk CBt (fp16 MMA)
    cbt_tc<<<dim3(2, NCH), 256, CBT_SMEM>>>();

    // 5) states (fp16 MMA, fp16 out)
    states_tc<<<dim3(NCH, NH), 256, ST_SMEM>>>();

    // 6) inter-chunk scan
    scan_kernel<<<4096, 256>>>();

    // 7) fused y (fp16 MMA)
    y_tc<<<dim3(NCH, NH), 256, YTC_SMEM>>>(Dp);

    // 8) gate + RMSNorm
    gate_norm_kernel<<<RW, 256>>>(norm_w);

    // convert W_out for GEMM2
    {
        long n4 = (long)DM * DI / 4;
        cvt_h1_kernel<<<(int)((n4 + 255) / 256), 256>>>(W_out, wo1, n4);
    }

    // 9) out-proj (fp16 GEMM 128x64, 2 CTAs/SM — wave-tail fix without spills)
    gemm_f16_n64<<<dim3(DM/64, RW/128), 256, NGEMM_SMEM>>>(yh, wo1, out, DI, DM);
}

// round 15
// speedup vs baseline: 1.0523x; 1.0523x over previous
#include <cuda_runtime.h>
#include <cuda_fp16.h>
#include <math.h>
#include <stdint.h>

// ---------------- problem constants ----------------
#define L_   4096
#define DM   2048          // D_MODEL
#define DI   4096          // D_INNER
#define NH   64            // N_HEADS
#define DH   64            // D_HEAD
#define NS   128           // D_STATE
#define CD   4352          // CONV_DIM
#define DPJ  8512          // D_IN_PROJ
#define DPJA 8704          // padded to 68*128 for GEMM tiles
#define CK   256           // CHUNK
#define NCH  32            // total chunks
#define RW   8192          // total rows = B*L

// ---------------- scratch (device globals; no allocations) ----------------
__device__ __half g_zxh[(size_t)RW * DPJA];    // in-proj output (fp16)
__device__ __half g_xBC[(size_t)RW * CD];      // conv+silu output (fp16)
__device__ float g_dt[RW * NH];
__device__ float g_dacs[RW * NH];
__device__ float g_CBt[NCH * CK * CK];
__device__ float g_states[(size_t)NCH * NH * DH * NS];
__device__ __half g_prev[(size_t)NCH * NH * DH * NS];
__device__ __half g_y[(size_t)RW * DI];
// fp16 GEMM operands
__device__ __half g_uh[(size_t)RW * DM];
__device__ __half g_wi1[(size_t)DPJA * DM];
__device__ __half g_yh[(size_t)RW * DI];
__device__ __half g_wo1[(size_t)DM * DI];

// ================= PTX helpers =================
__device__ __forceinline__ uint32_t smem_u32(const void* p) {
    uint32_t a;
    asm("{ .reg .u64 t; cvta.to.shared.u64 t, %1; cvt.u32.u64 %0, t; }" : "=r"(a) : "l"(p));
    return a;
}
#define CPA16(dst, src) \
    asm volatile("cp.async.cg.shared.global [%0], [%1], 16;" :: "r"(dst), "l"(src) : "memory")

#define LDSM4(r, adr)                                                            \
    asm volatile("ldmatrix.sync.aligned.m8n8.x4.shared.b16 {%0,%1,%2,%3}, [%4];" \
        : "=r"((r)[0]), "=r"((r)[1]), "=r"((r)[2]), "=r"((r)[3]) : "r"(adr))

#define MMAF16(c, a, b0, b1)                                                     \
    asm volatile("mma.sync.aligned.m16n8k16.row.col.f32.f16.f16.f32 "            \
        "{%0,%1,%2,%3}, {%4,%5,%6,%7}, {%8,%9}, {%0,%1,%2,%3};"                  \
        : "+f"((c)[0]), "+f"((c)[1]), "+f"((c)[2]), "+f"((c)[3])                  \
        : "r"((a)[0]), "r"((a)[1]), "r"((a)[2]), "r"((a)[3]), "r"(b0), "r"(b1))

// ================= conversion kernels =================
__global__ __launch_bounds__(256) void cvt_h1_kernel(
    const float* __restrict__ src, __half* __restrict__ dst, long n4)
{
    long i = (long)blockIdx.x * 256 + threadIdx.x;
    if (i >= n4) return;
    float4 v = ((const float4*)src)[i];
    ((__half2*)dst)[2*i]   = __halves2half2(__float2half_rn(v.x), __float2half_rn(v.y));
    ((__half2*)dst)[2*i+1] = __halves2half2(__float2half_rn(v.z), __float2half_rn(v.w));
}

__global__ __launch_bounds__(256) void cvt_h1_pad_kernel(
    const float* __restrict__ src, __half* __restrict__ dst,
    long n4, long rows_src, long cols4)
{
    long i = (long)blockIdx.x * 256 + threadIdx.x;
    if (i >= n4) return;
    float4 v = make_float4(0.f, 0.f, 0.f, 0.f);
    if (i / cols4 < rows_src) v = ((const float4*)src)[i];
    ((__half2*)dst)[2*i]   = __halves2half2(__float2half_rn(v.x), __float2half_rn(v.y));
    ((__half2*)dst)[2*i+1] = __halves2half2(__float2half_rn(v.z), __float2half_rn(v.w));
}

// ================= fp16 1-pass NT GEMM 128x128 =================
#define FSTAGES 3
#define FROWH 40
#define FTILE (128 * FROWH)
#define FSTAGE (2 * FTILE)
#define FGEMM_SMEM (FSTAGES * FSTAGE * 2)

template <bool OUTH>
__global__ __launch_bounds__(256, 2) void gemm_f16(
    const __half* __restrict__ A1, const __half* __restrict__ B1,
    void* __restrict__ Cv, int Ktot, int ldc)
{
    extern __shared__ __half fsm[];
    const int tid = threadIdx.x;
    const int wid = tid >> 5;
    const int lane = tid & 31;

    const int m0 = blockIdx.y * 128;
    const int n0 = blockIdx.x * 128;

    const int lrow = tid >> 2;
    const int lch  = (tid & 3) * 8;

    const __half* a1p = A1 + (size_t)m0 * Ktot;
    const __half* b1p = B1 + (size_t)n0 * Ktot;

    auto load_stage = [&](int s, int k0) {
        __half* st = fsm + s * FSTAGE;
#pragma unroll
        for (int q = 0; q < 2; q++) {
            int row = lrow + q * 64;
            uint32_t d = smem_u32(st + row * FROWH + lch);
            CPA16(d,             a1p + (size_t)row * Ktot + k0 + lch);
            CPA16(d + FTILE * 2, b1p + (size_t)row * Ktot + k0 + lch);
        }
        asm volatile("cp.async.commit_group;" ::: "memory");
    };

    const int wm = (wid & 1) * 64;
    const int wn = (wid >> 1) * 32;
    const int fr = lane & 15;
    const int fch = (lane >> 4) * 8;

    float acc[4][4][4];
#pragma unroll
    for (int a = 0; a < 4; a++)
#pragma unroll
        for (int b = 0; b < 4; b++)
#pragma unroll
            for (int c = 0; c < 4; c++) acc[a][b][c] = 0.f;

    const int KT = Ktot / 32;
    load_stage(0, 0);
    load_stage(1, 32);

    int cur = 0, nxt = 2;
    for (int kt = 0; kt < KT; kt++) {
        if (kt < KT - 1) {
            asm volatile("cp.async.wait_group 1;" ::: "memory");
        } else {
            asm volatile("cp.async.wait_group 0;" ::: "memory");
        }
        __syncthreads();
        if (kt + 2 < KT) load_stage(nxt, (kt + 2) * 32);

        const __half* st = fsm + cur * FSTAGE;
#pragma unroll
        for (int kk = 0; kk < 2; kk++) {
            const int kof = kk * 16;
            uint32_t af[4][4];
#pragma unroll
            for (int mb = 0; mb < 4; mb++) {
                uint32_t adr = smem_u32(st + (wm + mb * 16 + fr) * FROWH + kof + fch);
                LDSM4(af[mb], adr);
            }
            uint32_t bf[2][4];
#pragma unroll
            for (int nb2 = 0; nb2 < 2; nb2++) {
                uint32_t adr = smem_u32(st + FTILE + (wn + nb2 * 16 + fr) * FROWH + kof + fch);
                LDSM4(bf[nb2], adr);
            }
#pragma unroll
            for (int mb = 0; mb < 4; mb++)
#pragma unroll
                for (int nb = 0; nb < 4; nb++)
                    MMAF16(acc[mb][nb], af[mb], bf[nb >> 1][nb & 1], bf[nb >> 1][(nb & 1) + 2]);
        }
        cur = (cur == 2) ? 0 : cur + 1;
        nxt = (nxt == 2) ? 0 : nxt + 1;
    }

    const int er = lane >> 2;
    const int ec = (lane & 3) * 2;
#pragma unroll
    for (int mb = 0; mb < 4; mb++) {
#pragma unroll
        for (int nb = 0; nb < 4; nb++) {
            const size_t r0 = (size_t)(m0 + wm + mb * 16 + er) * ldc + n0 + wn + nb * 8 + ec;
            const size_t r1 = r0 + (size_t)8 * ldc;
            if (OUTH) {
                __half* C = (__half*)Cv;
                *(__half2*)&C[r0] = __halves2half2(__float2half_rn(acc[mb][nb][0]),
                                                   __float2half_rn(acc[mb][nb][1]));
                *(__half2*)&C[r1] = __halves2half2(__float2half_rn(acc[mb][nb][2]),
                                                   __float2half_rn(acc[mb][nb][3]));
            } else {
                float* C = (float*)Cv;
                *(float2*)&C[r0] = make_float2(acc[mb][nb][0], acc[mb][nb][1]);
                *(float2*)&C[r1] = make_float2(acc[mb][nb][2], acc[mb][nb][3]);
            }
        }
    }
}

// ---------------- per-chunk CBt via fp16 MMA ----------------
#define CBT_SMEM ((128*136 + 256*136) * 2)

__global__ __launch_bounds__(256, 1) void cbt_tc()
{
    extern __shared__ __half csm[];
    __half* Bs = csm;
    __half* Cs = csm + 128 * 136;

    const int chunk = blockIdx.y, j0 = blockIdx.x * 128, base = chunk * CK;
    const int tid = threadIdx.x;

#pragma unroll
    for (int e = 0; e < 8; e++) {
        int idx = tid + e * 256;
        int r = idx >> 4, c8 = (idx & 15) * 8;
        *(uint4*)&Bs[r * 136 + c8] =
            *(const uint4*)&g_xBC[(size_t)(base + j0 + r) * CD + DI + c8];
    }
#pragma unroll
    for (int e = 0; e < 16; e++) {
        int idx = tid + e * 256;
        int r = idx >> 4, c8 = (idx & 15) * 8;
        *(uint4*)&Cs[r * 136 + c8] =
            *(const uint4*)&g_xBC[(size_t)(base + r) * CD + DI + NS + c8];
    }
    __syncthreads();

    const int wid = tid >> 5, lane = tid & 31;
    const int wm = (wid & 1) * 64;
    const int wn = (wid >> 1) * 64;
    const int fr = lane & 15, fch = (lane >> 4) * 8;

    float acc[4][8][4];
#pragma unroll
    for (int a = 0; a < 4; a++)
#pragma unroll
        for (int b = 0; b < 8; b++)
#pragma unroll
            for (int c = 0; c < 4; c++) acc[a][b][c] = 0.f;

#pragma unroll
    for (int ks = 0; ks < 8; ks++) {
        uint32_t af[4][4];
#pragma unroll
        for (int mb = 0; mb < 4; mb++)
            LDSM4(af[mb], smem_u32(Bs + (wm + mb * 16 + fr) * 136 + ks * 16 + fch));
        uint32_t bf[4][4];
#pragma unroll
        for (int nb2 = 0; nb2 < 4; nb2++)
            LDSM4(bf[nb2], smem_u32(Cs + (wn + nb2 * 16 + fr) * 136 + ks * 16 + fch));
#pragma unroll
        for (int mb = 0; mb < 4; mb++)
#pragma unroll
            for (int nb = 0; nb < 8; nb++)
                MMAF16(acc[mb][nb], af[mb], bf[nb >> 1][nb & 1], bf[nb >> 1][(nb & 1) + 2]);
    }

    float* cbt = g_CBt + (size_t)chunk * CK * CK;
    const int er = lane >> 2, ec = (lane & 3) * 2;
#pragma unroll
    for (int mb = 0; mb < 4; mb++) {
        int j = j0 + wm + mb * 16 + er;
#pragma unroll
        for (int nb = 0; nb < 8; nb++) {
            int i = wn + nb * 8 + ec;
            *(float2*)&cbt[(size_t)j * CK + i] = make_float2(acc[mb][nb][0], acc[mb][nb][1]);
            *(float2*)&cbt[(size_t)(j + 8) * CK + i] = make_float2(acc[mb][nb][2], acc[mb][nb][3]);
        }
    }
}

// ---------------- tiled causal depthwise conv (width 4) + SiLU (fp16 in/out) ----------------
#define CT_ROWS 16
__global__ __launch_bounds__(256) void conv_silu_kernel(const float* __restrict__ conv_w,
                                                        const float* __restrict__ conv_b)
{
    __shared__ float ts[CT_ROWS + 3][256];
    const int c0 = blockIdx.x * 256;
    const int r0 = blockIdx.y * CT_ROWS;
    const int tid = threadIdx.x;
    const int cc = c0 + tid;
    const int batch_start = r0 & ~(L_ - 1);

    const __half* src = g_zxh + DI + cc;
#pragma unroll
    for (int rr = 0; rr < CT_ROWS + 3; rr++) {
        int x = r0 - 3 + rr;
        ts[rr][tid] = (x >= batch_start) ? __half2float(src[(size_t)x * DPJA]) : 0.f;
    }
    __syncthreads();

    const float cw0 = conv_w[cc*4+0], cw1 = conv_w[cc*4+1];
    const float cw2 = conv_w[cc*4+2], cw3 = conv_w[cc*4+3];
    const float cb = conv_b[cc];
#pragma unroll
    for (int rr = 0; rr < CT_ROWS; rr++) {
        float acc = cb + ts[rr][tid]*cw0 + ts[rr+1][tid]*cw1
                       + ts[rr+2][tid]*cw2 + ts[rr+3][tid]*cw3;
        float s = acc / (1.0f + __expf(-acc));
        g_xBC[(size_t)(r0 + rr) * CD + cc] = __float2half_rn(s);
    }
}

// ---------------- dt softplus + within-chunk cumsum (parallel scan) ----------------
__global__ __launch_bounds__(256) void dt_cumsum_kernel(const float* __restrict__ dt_bias,
                                                        const float* __restrict__ A_log)
{
    __shared__ float wsum[8];
    const int chunk = blockIdx.x;
    const int h = blockIdx.y;
    const int i = threadIdx.x;
    const int lane = i & 31, wid = i >> 5;
    const int r = chunk * CK + i;

    float Ahd = -expf(A_log[h]);
    float x = __half2float(g_zxh[(size_t)r * DPJA + DI + CD + h]) + dt_bias[h];
    float dt = fmaxf(x, 0.f) + log1pf(expf(-fabsf(x)));
    g_dt[r*NH + h] = dt;

    float v = dt * Ahd;
#pragma unroll
    for (int o = 1; o < 32; o <<= 1) {
        float n = __shfl_up_sync(0xffffffffu, v, o);
        if (lane >= o) v += n;
    }
    if (lane == 31) wsum[wid] = v;
    __syncthreads();
    float add = 0.f;
#pragma unroll
    for (int wq = 0; wq < 8; wq++) {
        float ws = wsum[wq];
        add += (wq < wid) ? ws : 0.f;
    }
    g_dacs[r*NH + h] = v + add;
}

// ---------------- states via fp16 MMA (fp32 output) ----------------
#define ST_SMEM (1024 + 64*264*2 + 128*264*2)

__global__ __launch_bounds__(256, 2) void states_tc()
{
    extern __shared__ char sm0[];
    float* ws = (float*)sm0;
    __half* At = (__half*)(sm0 + 1024);
    __half* Bt = (__half*)(sm0 + 1024 + 64*264*2);

    const int chunk = blockIdx.x, h = blockIdx.y, base = chunk * CK;
    const int tid = threadIdx.x;

    {
        float dl = g_dacs[(base + CK - 1)*NH + h];
        float dv = g_dacs[(base + tid)*NH + h];
        ws[tid] = __expf(dl - dv) * g_dt[(base + tid)*NH + h];
    }
    __syncthreads();

#pragma unroll 4
    for (int e = 0; e < 64; e++) {
        int idx = tid + e * 256;
        int p = idx & 63, s = idx >> 6;
        float x = __half2float(g_xBC[(size_t)(base + s) * CD + h * 64 + p]);
        At[p * 264 + s] = __float2half_rn(ws[s] * x);
    }
#pragma unroll 4
    for (int e = 0; e < 128; e++) {
        int idx = tid + e * 256;
        int n = idx & 127, s = idx >> 7;
        Bt[n * 264 + s] = g_xBC[(size_t)(base + s) * CD + DI + n];
    }
    __syncthreads();

    const int wid = tid >> 5, lane = tid & 31;
    const int wm = (wid & 1) * 32;
    const int wn = (wid >> 1) * 32;
    const int fr = lane & 15, fch = (lane >> 4) * 8;

    float acc[2][4][4];
#pragma unroll
    for (int a = 0; a < 2; a++)
#pragma unroll
        for (int b = 0; b < 4; b++)
#pragma unroll
            for (int c = 0; c < 4; c++) acc[a][b][c] = 0.f;

#pragma unroll
    for (int ks = 0; ks < 16; ks++) {
        uint32_t af[2][4];
#pragma unroll
        for (int mb = 0; mb < 2; mb++)
            LDSM4(af[mb], smem_u32(At + (wm + mb * 16 + fr) * 264 + ks * 16 + fch));
        uint32_t bf[2][4];
#pragma unroll
        for (int nb2 = 0; nb2 < 2; nb2++)
            LDSM4(bf[nb2], smem_u32(Bt + (wn + nb2 * 16 + fr) * 264 + ks * 16 + fch));
#pragma unroll
        for (int mb = 0; mb < 2; mb++)
#pragma unroll
            for (int nb = 0; nb < 4; nb++)
                MMAF16(acc[mb][nb], af[mb], bf[nb >> 1][nb & 1], bf[nb >> 1][(nb & 1) + 2]);
    }

    size_t obase = (size_t)(chunk * NH + h) * DH * NS;
    const int er = lane >> 2, ec = (lane & 3) * 2;
#pragma unroll
    for (int mb = 0; mb < 2; mb++) {
        int p0 = wm + mb * 16 + er;
#pragma unroll
        for (int nb = 0; nb < 4; nb++) {
            int col = wn + nb * 8 + ec;
            *(float2*)&g_states[obase + (size_t)p0 * NS + col] =
                make_float2(acc[mb][nb][0], acc[mb][nb][1]);
            *(float2*)&g_states[obase + (size_t)(p0 + 8) * NS + col] =
                make_float2(acc[mb][nb][2], acc[mb][nb][3]);
        }
    }
}

// ---------------- inter-chunk scan (vectorized: 2 elems/thread) ----------------
__global__ void scan_kernel()
{
    int idx = blockIdx.x * 256 + threadIdx.x;    // 0..524287
    int h = (idx >> 12) & 63;
    int b = idx >> 18;
    int pr = idx & 4095;                         // pair index within (b,h)
    float sx = 0.f, sy = 0.f;
    for (int c = 0; c < 16; c++) {
        size_t off = ((size_t)(b*16 + c)*NH + h)*DH*NS + 2*pr;
        *(__half2*)&g_prev[off] = __floats2half2_rn(sx, sy);
        float dec = __expf(g_dacs[(size_t)(b*L_ + c*CK + CK - 1)*NH + h]);
        float2 st = *(const float2*)&g_states[off];
        sx = sx * dec + st.x;
        sy = sy * dec + st.y;
    }
}

// ---------------- y via fp16 MMA (fp16 in/out) ----------------
#define YTC_SMEM 76288

__global__ __launch_bounds__(256, 2) void y_tc(const float* __restrict__ Dp)
{
    extern __shared__ char sm1[];
    float* das  = (float*)sm1;
    float* q    = das + 256;
    float* rqd  = q + 256;
    float* ei   = rqd + 256;
    float* Sarr = ei + 256;
    float* PP   = Sarr + 8;
    __half* xT    = (__half*)(sm1 + 4608);
    __half* prevB = (__half*)(sm1 + 38400);
    __half* Mt    = (__half*)(sm1 + 55808);

    const int chunk = blockIdx.x, h = blockIdx.y, base = chunk * CK;
    const int tid = threadIdx.x;
    const int wid = tid >> 5, lane = tid & 31;

    das[tid] = g_dacs[(base + tid)*NH + h];

#pragma unroll 4
    for (int e = 0; e < 64; e++) {
        int idx = tid + e * 256;
        int p = idx & 63, s = idx >> 6;
        xT[p * 264 + s] = g_xBC[(size_t)(base + s) * CD + h * 64 + p];
    }
    {
        size_t pb = (size_t)(chunk * NH + h) * DH * NS;
#pragma unroll 4
        for (int e = 0; e < 32; e++) {
            int idx = tid + e * 256;
            int p = idx >> 7, n = idx & 127;
            prevB[p * 136 + n] = g_prev[pb + idx];
        }
    }
    __syncthreads();
    {
        int si = tid >> 5;
        float ref = das[si * 32];
        float d = das[tid];
        q[tid]   = __expf(d - ref);
        rqd[tid] = __expf(ref - d) * g_dt[(base + tid)*NH + h];
        ei[tid]  = __expf(d);
        if (tid < 8)
            Sarr[tid] = (tid == 0) ? 1.f : __expf(das[tid*32] - das[tid*32 - 32]);
    }
    __syncthreads();
    if (tid < 64) {
        int si = tid >> 3, sj = tid & 7;
        float p = 0.f;
        if (si >= sj) {
            p = 1.f;
            for (int t = sj + 1; t <= si; t++) p *= Sarr[t];
        }
        PP[tid] = p;
    }
    __syncthreads();

    const int wm = (wid >> 1) * 64;
    const int wn = (wid & 1) * 32;
    const int fr = lane & 15, fch = (lane >> 4) * 8;

    float acc[4][4][4];
#pragma unroll
    for (int a = 0; a < 4; a++)
#pragma unroll
        for (int b = 0; b < 4; b++)
#pragma unroll
            for (int c = 0; c < 4; c++) acc[a][b][c] = 0.f;

    // ---- y_diag ----
    const float* cbb = g_CBt + (size_t)chunk * CK * CK;
    for (int jt = 0; jt < 8; jt++) {
        const int j0 = jt * 32;
        {
            const int i = tid;
            const float fq = q[i] * PP[(i >> 5) * 8 + jt];
            const float* cbp = cbb + (size_t)j0 * CK + i;
            __half2* mrow = (__half2*)(Mt + i * 40);
#pragma unroll
            for (int jp = 0; jp < 16; jp++) {
                int j  = 2 * jp;
                int jj = j0 + j;
                float v0 = (jj     <= i) ? cbp[(size_t)j * CK]     * fq * rqd[jj]     : 0.f;
                float v1 = (jj + 1 <= i) ? cbp[(size_t)(j+1) * CK] * fq * rqd[jj + 1] : 0.f;
                mrow[jp] = __halves2half2(__float2half_rn(v0), __float2half_rn(v1));
            }
        }
        __syncthreads();
        if (j0 < wm + 64) {
#pragma unroll
            for (int kk = 0; kk < 2; kk++) {
                uint32_t af[4][4];
#pragma unroll
                for (int mb = 0; mb < 4; mb++)
                    LDSM4(af[mb], smem_u32(Mt + (wm + mb * 16 + fr) * 40 + kk * 16 + fch));
                uint32_t bf[2][4];
#pragma unroll
                for (int nb2 = 0; nb2 < 2; nb2++)
                    LDSM4(bf[nb2], smem_u32(xT + (wn + nb2 * 16 + fr) * 264 + j0 + kk * 16 + fch));
#pragma unroll
                for (int mb = 0; mb < 4; mb++)
#pragma unroll
                    for (int nb = 0; nb < 4; nb++)
                        MMAF16(acc[mb][nb], af[mb], bf[nb >> 1][nb & 1], bf[nb >> 1][(nb & 1) + 2]);
            }
        }
        __syncthreads();
    }

    // ---- y_off ----
    for (int nt = 0; nt < 4; nt++) {
        const int n0 = nt * 32;
        {
            const int i = tid;
            const float e = ei[i];
            const __half2* cp2 = (const __half2*)&g_xBC[(size_t)(base + i) * CD + DI + NS + n0];
            __half2* mrow = (__half2*)(Mt + i * 40);
#pragma unroll
            for (int j2 = 0; j2 < 16; j2++) {
                __half2 v = cp2[j2];
                mrow[j2] = __floats2half2_rn(e * __low2float(v), e * __high2float(v));
            }
        }
        __syncthreads();
#pragma unroll
        for (int kk = 0; kk < 2; kk++) {
            uint32_t af[4][4];
#pragma unroll
            for (int mb = 0; mb < 4; mb++)
                LDSM4(af[mb], smem_u32(Mt + (wm + mb * 16 + fr) * 40 + kk * 16 + fch));
            uint32_t bf[2][4];
#pragma unroll
            for (int nb2 = 0; nb2 < 2; nb2++)
                LDSM4(bf[nb2], smem_u32(prevB + (wn + nb2 * 16 + fr) * 136 + n0 + kk * 16 + fch));
#pragma unroll
            for (int mb = 0; mb < 4; mb++)
#pragma unroll
                for (int nb = 0; nb < 4; nb++)
                    MMAF16(acc[mb][nb], af[mb], bf[nb >> 1][nb & 1], bf[nb >> 1][(nb & 1) + 2]);
        }
        __syncthreads();
    }

    // ---- epilogue ----
    const float dph = Dp[h];
    const int er = lane >> 2, ec = (lane & 3) * 2;
#pragma unroll
    for (int mb = 0; mb < 4; mb++) {
        int i0 = wm + mb * 16 + er;
#pragma unroll
        for (int nb = 0; nb < 4; nb++) {
            int p = wn + nb * 8 + ec;
            float x00 = __half2float(xT[(size_t)p * 264 + i0]);
            float x01 = __half2float(xT[(size_t)(p + 1) * 264 + i0]);
            float x10 = __half2float(xT[(size_t)p * 264 + i0 + 8]);
            float x11 = __half2float(xT[(size_t)(p + 1) * 264 + i0 + 8]);
            *(__half2*)&g_y[(size_t)(base + i0) * DI + h * 64 + p] =
                __halves2half2(__float2half_rn(acc[mb][nb][0] + dph * x00),
                               __float2half_rn(acc[mb][nb][1] + dph * x01));
            *(__half2*)&g_y[(size_t)(base + i0 + 8) * DI + h * 64 + p] =
                __halves2half2(__float2half_rn(acc[mb][nb][2] + dph * x10),
                               __float2half_rn(acc[mb][nb][3] + dph * x11));
        }
    }
}

// ---------------- gate (silu(z)) + RMSNorm; vectorized half2 ----------------
__global__ __launch_bounds__(256) void gate_norm_kernel(const float* __restrict__ norm_w)
{
    __shared__ float buf[DI];
    __shared__ float red[8];
    int r = blockIdx.x;
    int tid = threadIdx.x;
    const __half2* yrow = (const __half2*)&g_y[(size_t)r * DI];
    const __half2* zrow = (const __half2*)&g_zxh[(size_t)r * DPJA];
    float ss = 0.f;
#pragma unroll
    for (int e = 0; e < 8; e++) {
        int c2 = tid + e * 256;             // half2 index 0..2047
        float2 y = __half22float2(yrow[c2]);
        float2 z = __half22float2(zrow[c2]);
        float g0 = y.x * (z.x / (1.f + __expf(-z.x)));
        float g1 = y.y * (z.y / (1.f + __expf(-z.y)));
        buf[2*c2]   = g0;
        buf[2*c2+1] = g1;
        ss += g0*g0 + g1*g1;
    }
#pragma unroll
    for (int o = 16; o > 0; o >>= 1) ss += __shfl_xor_sync(0xffffffffu, ss, o);
    if ((tid & 31) == 0) red[tid >> 5] = ss;
    __syncthreads();
    float tot = 0.f;
#pragma unroll
    for (int q = 0; q < 8; q++) tot += red[q];
    float scale = rsqrtf(tot / (float)DI + 1e-5f);
    __half2* orow = (__half2*)&g_yh[(size_t)r * DI];
#pragma unroll
    for (int e = 0; e < 8; e++) {
        int c2 = tid + e * 256;
        float g0 = buf[2*c2]   * scale * norm_w[2*c2];
        float g1 = buf[2*c2+1] * scale * norm_w[2*c2+1];
        orow[c2] = __floats2half2_rn(g0, g1);
    }
}

// ---------------- launch ----------------
extern "C" void kernel_launch(void* const* d_in, const int* in_sizes, int n_in,
                              void* d_out, int out_size)
{
    const float* u       = (const float*)d_in[0];
    const float* W_in    = (const float*)d_in[1];
    const float* conv_w  = (const float*)d_in[2];
    const float* conv_b  = (const float*)d_in[3];
    const float* dt_bias = (const float*)d_in[4];
    const float* A_log   = (const float*)d_in[5];
    const float* Dp      = (const float*)d_in[6];
    const float* norm_w  = (const float*)d_in[7];
    const float* W_out   = (const float*)d_in[8];
    float* out = (float*)d_out;

    __half *zxh, *uh, *wi1, *yh, *wo1;
    cudaGetSymbolAddress((void**)&zxh, g_zxh);
    cudaGetSymbolAddress((void**)&uh,  g_uh);
    cudaGetSymbolAddress((void**)&wi1, g_wi1);
    cudaGetSymbolAddress((void**)&yh,  g_yh);
    cudaGetSymbolAddress((void**)&wo1, g_wo1);

    cudaFuncSetAttribute(gemm_f16<true>,  cudaFuncAttributeMaxDynamicSharedMemorySize, FGEMM_SMEM);
    cudaFuncSetAttribute(gemm_f16<false>, cudaFuncAttributeMaxDynamicSharedMemorySize, FGEMM_SMEM);
    cudaFuncSetAttribute(cbt_tc,    cudaFuncAttributeMaxDynamicSharedMemorySize, CBT_SMEM);
    cudaFuncSetAttribute(states_tc, cudaFuncAttributeMaxDynamicSharedMemorySize, ST_SMEM);
    cudaFuncSetAttribute(y_tc,      cudaFuncAttributeMaxDynamicSharedMemorySize, YTC_SMEM);

    // side stream + events (host-side objects only; no device allocations)
    cudaStream_t s2;
    cudaStreamCreateWithFlags(&s2, cudaStreamNonBlocking);
    cudaEvent_t ev0, ev_wo, ev_g1, ev_dt, ev_conv, ev_cbt;
    cudaEventCreateWithFlags(&ev0,     cudaEventDisableTiming);
    cudaEventCreateWithFlags(&ev_wo,   cudaEventDisableTiming);
    cudaEventCreateWithFlags(&ev_g1,   cudaEventDisableTiming);
    cudaEventCreateWithFlags(&ev_dt,   cudaEventDisableTiming);
    cudaEventCreateWithFlags(&ev_conv, cudaEventDisableTiming);
    cudaEventCreateWithFlags(&ev_cbt,  cudaEventDisableTiming);

    // fork side stream from origin
    cudaEventRecord(ev0, 0);
    cudaStreamWaitEvent(s2, ev0, 0);

    // s2: convert W_out (fully independent of the main chain)
    {
        long n4 = (long)DM * DI / 4;
        cvt_h1_kernel<<<(int)((n4 + 255) / 256), 256, 0, s2>>>(W_out, wo1, n4);
        cudaEventRecord(ev_wo, s2);
    }

    // s0: convert inputs for GEMM1
    {
        long n4 = (long)RW * DM / 4;
        cvt_h1_kernel<<<(int)((n4 + 255) / 256), 256>>>(u, uh, n4);
    }
    {
        long n4 = (long)DPJA * DM / 4;
        cvt_h1_pad_kernel<<<(int)((n4 + 255) / 256), 256>>>(W_in, wi1, n4, DPJ, DM/4);
    }

    // 1) in-proj (fp16 GEMM 128x128, fp16 output)
    gemm_f16<true><<<dim3(DPJA/128, RW/128), 256, FGEMM_SMEM>>>(uh, wi1, zxh, DM, DPJA);
    cudaEventRecord(ev_g1, 0);

    // s2: dt softplus + cumsum (depends only on GEMM1; overlaps conv)
    cudaStreamWaitEvent(s2, ev_g1, 0);
    dt_cumsum_kernel<<<dim3(NCH, NH), 256, 0, s2>>>(dt_bias, A_log);
    cudaEventRecord(ev_dt, s2);

    // 2) conv + silu (s0)
    conv_silu_kernel<<<dim3(CD/256, RW/CT_ROWS), 256>>>(conv_w, conv_b);
    cudaEventRecord(ev_conv, 0);

    // s2: per-chunk CBt (depends on conv; overlaps states/scan)
    cudaStreamWaitEvent(s2, ev_conv, 0);
    cbt_tc<<<dim3(2, NCH), 256, CBT_SMEM, s2>>>();
    cudaEventRecord(ev_cbt, s2);

    // s0: states (needs conv + dt)
    cudaStreamWaitEvent(0, ev_dt, 0);
    states_tc<<<dim3(NCH, NH), 256, ST_SMEM>>>();

    // s0: inter-chunk scan
    scan_kernel<<<2048, 256>>>();

    // s0: fused y (needs scan + cbt)
    cudaStreamWaitEvent(0, ev_cbt, 0);
    y_tc<<<dim3(NCH, NH), 256, YTC_SMEM>>>(Dp);

    // s0: gate + RMSNorm
    gate_norm_kernel<<<RW, 256>>>(norm_w);

    // s0: out-proj (needs gate_norm + W_out conversion)
    cudaStreamWaitEvent(0, ev_wo, 0);
    gemm_f16<false><<<dim3(DM/128, RW/128), 256, FGEMM_SMEM>>>(yh, wo1, out, DI, DM);
}

// round 17
// speedup vs baseline: 1.0539x; 1.0015x over previous
#include <cuda_runtime.h>
#include <cuda_fp16.h>
#include <math.h>
#include <stdint.h>

// ---------------- problem constants ----------------
#define L_   4096
#define DM   2048          // D_MODEL
#define DI   4096          // D_INNER
#define NH   64            // N_HEADS
#define DH   64            // D_HEAD
#define NS   128           // D_STATE
#define CD   4352          // CONV_DIM
#define DPJ  8512          // D_IN_PROJ
#define DPJA 8704          // padded to 68*128 for GEMM tiles
#define CK   256           // CHUNK
#define NCH  32            // total chunks
#define RW   8192          // total rows = B*L

// ---------------- scratch (device globals; no allocations) ----------------
__device__ __half g_zxh[(size_t)RW * DPJA];    // in-proj output (fp16)
__device__ __half g_xBC[(size_t)RW * CD];      // conv+silu output (fp16)
__device__ float g_dt[RW * NH];
__device__ float g_dacs[RW * NH];
__device__ float g_CBt[NCH * CK * CK];
__device__ float g_states[(size_t)NCH * NH * DH * NS];
__device__ __half g_prev[(size_t)NCH * NH * DH * NS];
__device__ __half g_y[(size_t)RW * DI];
// fp16 GEMM operands
__device__ __half g_uh[(size_t)RW * DM];
__device__ __half g_wi1[(size_t)DPJA * DM];
__device__ __half g_yh[(size_t)RW * DI];
__device__ __half g_wo1[(size_t)DM * DI];

// ================= PTX helpers =================
__device__ __forceinline__ uint32_t smem_u32(const void* p) {
    uint32_t a;
    asm("{ .reg .u64 t; cvta.to.shared.u64 t, %1; cvt.u32.u64 %0, t; }" : "=r"(a) : "l"(p));
    return a;
}
#define CPA16(dst, src) \
    asm volatile("cp.async.cg.shared.global [%0], [%1], 16;" :: "r"(dst), "l"(src) : "memory")

#define LDSM4(r, adr)                                                            \
    asm volatile("ldmatrix.sync.aligned.m8n8.x4.shared.b16 {%0,%1,%2,%3}, [%4];" \
        : "=r"((r)[0]), "=r"((r)[1]), "=r"((r)[2]), "=r"((r)[3]) : "r"(adr))

#define MMAF16(c, a, b0, b1)                                                     \
    asm volatile("mma.sync.aligned.m16n8k16.row.col.f32.f16.f16.f32 "            \
        "{%0,%1,%2,%3}, {%4,%5,%6,%7}, {%8,%9}, {%0,%1,%2,%3};"                  \
        : "+f"((c)[0]), "+f"((c)[1]), "+f"((c)[2]), "+f"((c)[3])                  \
        : "r"((a)[0]), "r"((a)[1]), "r"((a)[2]), "r"((a)[3]), "r"(b0), "r"(b1))

// ================= conversion kernels =================
__global__ __launch_bounds__(256) void cvt_h1_kernel(
    const float* __restrict__ src, __half* __restrict__ dst, long n4)
{
    long i = (long)blockIdx.x * 256 + threadIdx.x;
    if (i >= n4) return;
    float4 v = ((const float4*)src)[i];
    ((__half2*)dst)[2*i]   = __halves2half2(__float2half_rn(v.x), __float2half_rn(v.y));
    ((__half2*)dst)[2*i+1] = __halves2half2(__float2half_rn(v.z), __float2half_rn(v.w));
}

__global__ __launch_bounds__(256) void cvt_h1_pad_kernel(
    const float* __restrict__ src, __half* __restrict__ dst,
    long n4, long rows_src, long cols4)
{
    long i = (long)blockIdx.x * 256 + threadIdx.x;
    if (i >= n4) return;
    float4 v = make_float4(0.f, 0.f, 0.f, 0.f);
    if (i / cols4 < rows_src) v = ((const float4*)src)[i];
    ((__half2*)dst)[2*i]   = __halves2half2(__float2half_rn(v.x), __float2half_rn(v.y));
    ((__half2*)dst)[2*i+1] = __halves2half2(__float2half_rn(v.z), __float2half_rn(v.w));
}

// ================= fp16 1-pass NT GEMM 128x128 =================
#define FSTAGES 3
#define FROWH 40
#define FTILE (128 * FROWH)
#define FSTAGE (2 * FTILE)
#define FGEMM_SMEM (FSTAGES * FSTAGE * 2)

template <bool OUTH>
__global__ __launch_bounds__(256, 2) void gemm_f16(
    const __half* __restrict__ A1, const __half* __restrict__ B1,
    void* __restrict__ Cv, int Ktot, int ldc)
{
    extern __shared__ __half fsm[];
    const int tid = threadIdx.x;
    const int wid = tid >> 5;
    const int lane = tid & 31;

    const int m0 = blockIdx.y * 128;
    const int n0 = blockIdx.x * 128;

    const int lrow = tid >> 2;
    const int lch  = (tid & 3) * 8;

    const __half* a1p = A1 + (size_t)m0 * Ktot;
    const __half* b1p = B1 + (size_t)n0 * Ktot;

    auto load_stage = [&](int s, int k0) {
        __half* st = fsm + s * FSTAGE;
#pragma unroll
        for (int q = 0; q < 2; q++) {
            int row = lrow + q * 64;
            uint32_t d = smem_u32(st + row * FROWH + lch);
            CPA16(d,             a1p + (size_t)row * Ktot + k0 + lch);
            CPA16(d + FTILE * 2, b1p + (size_t)row * Ktot + k0 + lch);
        }
        asm volatile("cp.async.commit_group;" ::: "memory");
    };

    const int wm = (wid & 1) * 64;
    const int wn = (wid >> 1) * 32;
    const int fr = lane & 15;
    const int fch = (lane >> 4) * 8;

    float acc[4][4][4];
#pragma unroll
    for (int a = 0; a < 4; a++)
#pragma unroll
        for (int b = 0; b < 4; b++)
#pragma unroll
            for (int c = 0; c < 4; c++) acc[a][b][c] = 0.f;

    const int KT = Ktot / 32;
    load_stage(0, 0);
    load_stage(1, 32);

    int cur = 0, nxt = 2;
    for (int kt = 0; kt < KT; kt++) {
        if (kt < KT - 1) {
            asm volatile("cp.async.wait_group 1;" ::: "memory");
        } else {
            asm volatile("cp.async.wait_group 0;" ::: "memory");
        }
        __syncthreads();
        if (kt + 2 < KT) load_stage(nxt, (kt + 2) * 32);

        const __half* st = fsm + cur * FSTAGE;
#pragma unroll
        for (int kk = 0; kk < 2; kk++) {
            const int kof = kk * 16;
            uint32_t af[4][4];
#pragma unroll
            for (int mb = 0; mb < 4; mb++) {
                uint32_t adr = smem_u32(st + (wm + mb * 16 + fr) * FROWH + kof + fch);
                LDSM4(af[mb], adr);
            }
            uint32_t bf[2][4];
#pragma unroll
            for (int nb2 = 0; nb2 < 2; nb2++) {
                uint32_t adr = smem_u32(st + FTILE + (wn + nb2 * 16 + fr) * FROWH + kof + fch);
                LDSM4(bf[nb2], adr);
            }
#pragma unroll
            for (int mb = 0; mb < 4; mb++)
#pragma unroll
                for (int nb = 0; nb < 4; nb++)
                    MMAF16(acc[mb][nb], af[mb], bf[nb >> 1][nb & 1], bf[nb >> 1][(nb & 1) + 2]);
        }
        cur = (cur == 2) ? 0 : cur + 1;
        nxt = (nxt == 2) ? 0 : nxt + 1;
    }

    const int er = lane >> 2;
    const int ec = (lane & 3) * 2;
#pragma unroll
    for (int mb = 0; mb < 4; mb++) {
#pragma unroll
        for (int nb = 0; nb < 4; nb++) {
            const size_t r0 = (size_t)(m0 + wm + mb * 16 + er) * ldc + n0 + wn + nb * 8 + ec;
            const size_t r1 = r0 + (size_t)8 * ldc;
            if (OUTH) {
                __half* C = (__half*)Cv;
                *(__half2*)&C[r0] = __halves2half2(__float2half_rn(acc[mb][nb][0]),
                                                   __float2half_rn(acc[mb][nb][1]));
                *(__half2*)&C[r1] = __halves2half2(__float2half_rn(acc[mb][nb][2]),
                                                   __float2half_rn(acc[mb][nb][3]));
            } else {
                float* C = (float*)Cv;
                *(float2*)&C[r0] = make_float2(acc[mb][nb][0], acc[mb][nb][1]);
                *(float2*)&C[r1] = make_float2(acc[mb][nb][2], acc[mb][nb][3]);
            }
        }
    }
}

// ---------------- per-chunk CBt via fp16 MMA ----------------
#define CBT_SMEM ((128*136 + 256*136) * 2)

__global__ __launch_bounds__(256, 1) void cbt_tc()
{
    extern __shared__ __half csm[];
    __half* Bs = csm;
    __half* Cs = csm + 128 * 136;

    const int chunk = blockIdx.y, j0 = blockIdx.x * 128, base = chunk * CK;
    const int tid = threadIdx.x;

#pragma unroll
    for (int e = 0; e < 8; e++) {
        int idx = tid + e * 256;
        int r = idx >> 4, c8 = (idx & 15) * 8;
        *(uint4*)&Bs[r * 136 + c8] =
            *(const uint4*)&g_xBC[(size_t)(base + j0 + r) * CD + DI + c8];
    }
#pragma unroll
    for (int e = 0; e < 16; e++) {
        int idx = tid + e * 256;
        int r = idx >> 4, c8 = (idx & 15) * 8;
        *(uint4*)&Cs[r * 136 + c8] =
            *(const uint4*)&g_xBC[(size_t)(base + r) * CD + DI + NS + c8];
    }
    __syncthreads();

    const int wid = tid >> 5, lane = tid & 31;
    const int wm = (wid & 1) * 64;
    const int wn = (wid >> 1) * 64;
    const int fr = lane & 15, fch = (lane >> 4) * 8;

    float acc[4][8][4];
#pragma unroll
    for (int a = 0; a < 4; a++)
#pragma unroll
        for (int b = 0; b < 8; b++)
#pragma unroll
            for (int c = 0; c < 4; c++) acc[a][b][c] = 0.f;

#pragma unroll
    for (int ks = 0; ks < 8; ks++) {
        uint32_t af[4][4];
#pragma unroll
        for (int mb = 0; mb < 4; mb++)
            LDSM4(af[mb], smem_u32(Bs + (wm + mb * 16 + fr) * 136 + ks * 16 + fch));
        uint32_t bf[4][4];
#pragma unroll
        for (int nb2 = 0; nb2 < 4; nb2++)
            LDSM4(bf[nb2], smem_u32(Cs + (wn + nb2 * 16 + fr) * 136 + ks * 16 + fch));
#pragma unroll
        for (int mb = 0; mb < 4; mb++)
#pragma unroll
            for (int nb = 0; nb < 8; nb++)
                MMAF16(acc[mb][nb], af[mb], bf[nb >> 1][nb & 1], bf[nb >> 1][(nb & 1) + 2]);
    }

    float* cbt = g_CBt + (size_t)chunk * CK * CK;
    const int er = lane >> 2, ec = (lane & 3) * 2;
#pragma unroll
    for (int mb = 0; mb < 4; mb++) {
        int j = j0 + wm + mb * 16 + er;
#pragma unroll
        for (int nb = 0; nb < 8; nb++) {
            int i = wn + nb * 8 + ec;
            *(float2*)&cbt[(size_t)j * CK + i] = make_float2(acc[mb][nb][0], acc[mb][nb][1]);
            *(float2*)&cbt[(size_t)(j + 8) * CK + i] = make_float2(acc[mb][nb][2], acc[mb][nb][3]);
        }
    }
}

// ---------------- tiled causal depthwise conv (width 4) + SiLU (fp16 in/out) ----------------
#define CT_ROWS 16
__global__ __launch_bounds__(256) void conv_silu_kernel(const float* __restrict__ conv_w,
                                                        const float* __restrict__ conv_b)
{
    __shared__ float ts[CT_ROWS + 3][256];
    const int c0 = blockIdx.x * 256;
    const int r0 = blockIdx.y * CT_ROWS;
    const int tid = threadIdx.x;
    const int cc = c0 + tid;
    const int batch_start = r0 & ~(L_ - 1);

    const __half* src = g_zxh + DI + cc;
#pragma unroll
    for (int rr = 0; rr < CT_ROWS + 3; rr++) {
        int x = r0 - 3 + rr;
        ts[rr][tid] = (x >= batch_start) ? __half2float(src[(size_t)x * DPJA]) : 0.f;
    }
    __syncthreads();

    const float cw0 = conv_w[cc*4+0], cw1 = conv_w[cc*4+1];
    const float cw2 = conv_w[cc*4+2], cw3 = conv_w[cc*4+3];
    const float cb = conv_b[cc];
#pragma unroll
    for (int rr = 0; rr < CT_ROWS; rr++) {
        float acc = cb + ts[rr][tid]*cw0 + ts[rr+1][tid]*cw1
                       + ts[rr+2][tid]*cw2 + ts[rr+3][tid]*cw3;
        float s = acc / (1.0f + __expf(-acc));
        g_xBC[(size_t)(r0 + rr) * CD + cc] = __float2half_rn(s);
    }
}

// ---------------- dt softplus + within-chunk cumsum (parallel scan) ----------------
__global__ __launch_bounds__(256) void dt_cumsum_kernel(const float* __restrict__ dt_bias,
                                                        const float* __restrict__ A_log)
{
    __shared__ float wsum[8];
    const int chunk = blockIdx.x;
    const int h = blockIdx.y;
    const int i = threadIdx.x;
    const int lane = i & 31, wid = i >> 5;
    const int r = chunk * CK + i;

    float Ahd = -expf(A_log[h]);
    float x = __half2float(g_zxh[(size_t)r * DPJA + DI + CD + h]) + dt_bias[h];
    float dt = fmaxf(x, 0.f) + log1pf(expf(-fabsf(x)));
    g_dt[r*NH + h] = dt;

    float v = dt * Ahd;
#pragma unroll
    for (int o = 1; o < 32; o <<= 1) {
        float n = __shfl_up_sync(0xffffffffu, v, o);
        if (lane >= o) v += n;
    }
    if (lane == 31) wsum[wid] = v;
    __syncthreads();
    float add = 0.f;
#pragma unroll
    for (int wq = 0; wq < 8; wq++) {
        float ws = wsum[wq];
        add += (wq < wid) ? ws : 0.f;
    }
    g_dacs[r*NH + h] = v + add;
}

// ---------------- states via fp16 MMA (fp32 output) ----------------
#define ST_SMEM (1024 + 64*264*2 + 128*264*2)

__global__ __launch_bounds__(256, 2) void states_tc()
{
    extern __shared__ char sm0[];
    float* ws = (float*)sm0;
    __half* At = (__half*)(sm0 + 1024);
    __half* Bt = (__half*)(sm0 + 1024 + 64*264*2);

    const int chunk = blockIdx.x, h = blockIdx.y, base = chunk * CK;
    const int tid = threadIdx.x;

    {
        float dl = g_dacs[(base + CK - 1)*NH + h];
        float dv = g_dacs[(base + tid)*NH + h];
        ws[tid] = __expf(dl - dv) * g_dt[(base + tid)*NH + h];
    }
    __syncthreads();

#pragma unroll 4
    for (int e = 0; e < 64; e++) {
        int idx = tid + e * 256;
        int p = idx & 63, s = idx >> 6;
        float x = __half2float(g_xBC[(size_t)(base + s) * CD + h * 64 + p]);
        At[p * 264 + s] = __float2half_rn(ws[s] * x);
    }
#pragma unroll 4
    for (int e = 0; e < 128; e++) {
        int idx = tid + e * 256;
        int n = idx & 127, s = idx >> 7;
        Bt[n * 264 + s] = g_xBC[(size_t)(base + s) * CD + DI + n];
    }
    __syncthreads();

    const int wid = tid >> 5, lane = tid & 31;
    const int wm = (wid & 1) * 32;
    const int wn = (wid >> 1) * 32;
    const int fr = lane & 15, fch = (lane >> 4) * 8;

    float acc[2][4][4];
#pragma unroll
    for (int a = 0; a < 2; a++)
#pragma unroll
        for (int b = 0; b < 4; b++)
#pragma unroll
            for (int c = 0; c < 4; c++) acc[a][b][c] = 0.f;

#pragma unroll
    for (int ks = 0; ks < 16; ks++) {
        uint32_t af[2][4];
#pragma unroll
        for (int mb = 0; mb < 2; mb++)
            LDSM4(af[mb], smem_u32(At + (wm + mb * 16 + fr) * 264 + ks * 16 + fch));
        uint32_t bf[2][4];
#pragma unroll
        for (int nb2 = 0; nb2 < 2; nb2++)
            LDSM4(bf[nb2], smem_u32(Bt + (wn + nb2 * 16 + fr) * 264 + ks * 16 + fch));
#pragma unroll
        for (int mb = 0; mb < 2; mb++)
#pragma unroll
            for (int nb = 0; nb < 4; nb++)
                MMAF16(acc[mb][nb], af[mb], bf[nb >> 1][nb & 1], bf[nb >> 1][(nb & 1) + 2]);
    }

    size_t obase = (size_t)(chunk * NH + h) * DH * NS;
    const int er = lane >> 2, ec = (lane & 3) * 2;
#pragma unroll
    for (int mb = 0; mb < 2; mb++) {
        int p0 = wm + mb * 16 + er;
#pragma unroll
        for (int nb = 0; nb < 4; nb++) {
            int col = wn + nb * 8 + ec;
            *(float2*)&g_states[obase + (size_t)p0 * NS + col] =
                make_float2(acc[mb][nb][0], acc[mb][nb][1]);
            *(float2*)&g_states[obase + (size_t)(p0 + 8) * NS + col] =
                make_float2(acc[mb][nb][2], acc[mb][nb][3]);
        }
    }
}

// ---------------- inter-chunk scan (vectorized: 2 elems/thread) ----------------
__global__ void scan_kernel()
{
    int idx = blockIdx.x * 256 + threadIdx.x;
    int h = (idx >> 12) & 63;
    int b = idx >> 18;
    int pr = idx & 4095;
    float sx = 0.f, sy = 0.f;
    for (int c = 0; c < 16; c++) {
        size_t off = ((size_t)(b*16 + c)*NH + h)*DH*NS + 2*pr;
        *(__half2*)&g_prev[off] = __floats2half2_rn(sx, sy);
        float dec = __expf(g_dacs[(size_t)(b*L_ + c*CK + CK - 1)*NH + h]);
        float2 st = *(const float2*)&g_states[off];
        sx = sx * dec + st.x;
        sy = sy * dec + st.y;
    }
}

// ---------------- y via fp16 MMA (fp16 in/out) ----------------
#define YTC_SMEM 76288

__global__ __launch_bounds__(256, 2) void y_tc(const float* __restrict__ Dp)
{
    extern __shared__ char sm1[];
    float* das  = (float*)sm1;
    float* q    = das + 256;
    float* rqd  = q + 256;
    float* ei   = rqd + 256;
    float* Sarr = ei + 256;
    float* PP   = Sarr + 8;
    __half* xT    = (__half*)(sm1 + 4608);
    __half* prevB = (__half*)(sm1 + 38400);
    __half* Mt    = (__half*)(sm1 + 55808);

    const int chunk = blockIdx.x, h = blockIdx.y, base = chunk * CK;
    const int tid = threadIdx.x;
    const int wid = tid >> 5, lane = tid & 31;

    das[tid] = g_dacs[(base + tid)*NH + h];

#pragma unroll 4
    for (int e = 0; e < 64; e++) {
        int idx = tid + e * 256;
        int p = idx & 63, s = idx >> 6;
        xT[p * 264 + s] = g_xBC[(size_t)(base + s) * CD + h * 64 + p];
    }
    {
        size_t pb = (size_t)(chunk * NH + h) * DH * NS;
#pragma unroll 4
        for (int e = 0; e < 32; e++) {
            int idx = tid + e * 256;
            int p = idx >> 7, n = idx & 127;
            prevB[p * 136 + n] = g_prev[pb + idx];
        }
    }
    __syncthreads();
    {
        int si = tid >> 5;
        float ref = das[si * 32];
        float d = das[tid];
        q[tid]   = __expf(d - ref);
        rqd[tid] = __expf(ref - d) * g_dt[(base + tid)*NH + h];
        ei[tid]  = __expf(d);
        if (tid < 8)
            Sarr[tid] = (tid == 0) ? 1.f : __expf(das[tid*32] - das[tid*32 - 32]);
    }
    __syncthreads();
    if (tid < 64) {
        int si = tid >> 3, sj = tid & 7;
        float p = 0.f;
        if (si >= sj) {
            p = 1.f;
            for (int t = sj + 1; t <= si; t++) p *= Sarr[t];
        }
        PP[tid] = p;
    }
    __syncthreads();

    const int wm = (wid >> 1) * 64;
    const int wn = (wid & 1) * 32;
    const int fr = lane & 15, fch = (lane >> 4) * 8;

    float acc[4][4][4];
#pragma unroll
    for (int a = 0; a < 4; a++)
#pragma unroll
        for (int b = 0; b < 4; b++)
#pragma unroll
            for (int c = 0; c < 4; c++) acc[a][b][c] = 0.f;

    // ---- y_diag ----
    const float* cbb = g_CBt + (size_t)chunk * CK * CK;
    for (int jt = 0; jt < 8; jt++) {
        const int j0 = jt * 32;
        {
            const int i = tid;
            const float fq = q[i] * PP[(i >> 5) * 8 + jt];
            const float* cbp = cbb + (size_t)j0 * CK + i;
            __half2* mrow = (__half2*)(Mt + i * 40);
#pragma unroll
            for (int jp = 0; jp < 16; jp++) {
                int j  = 2 * jp;
                int jj = j0 + j;
                float v0 = (jj     <= i) ? cbp[(size_t)j * CK]     * fq * rqd[jj]     : 0.f;
                float v1 = (jj + 1 <= i) ? cbp[(size_t)(j+1) * CK] * fq * rqd[jj + 1] : 0.f;
                mrow[jp] = __halves2half2(__float2half_rn(v0), __float2half_rn(v1));
            }
        }
        __syncthreads();
        if (j0 < wm + 64) {
#pragma unroll
            for (int kk = 0; kk < 2; kk++) {
                uint32_t af[4][4];
#pragma unroll
                for (int mb = 0; mb < 4; mb++)
                    LDSM4(af[mb], smem_u32(Mt + (wm + mb * 16 + fr) * 40 + kk * 16 + fch));
                uint32_t bf[2][4];
#pragma unroll
                for (int nb2 = 0; nb2 < 2; nb2++)
                    LDSM4(bf[nb2], smem_u32(xT + (wn + nb2 * 16 + fr) * 264 + j0 + kk * 16 + fch));
#pragma unroll
                for (int mb = 0; mb < 4; mb++)
#pragma unroll
                    for (int nb = 0; nb < 4; nb++)
                        MMAF16(acc[mb][nb], af[mb], bf[nb >> 1][nb & 1], bf[nb >> 1][(nb & 1) + 2]);
            }
        }
        __syncthreads();
    }

    // ---- y_off ----
    for (int nt = 0; nt < 4; nt++) {
        const int n0 = nt * 32;
        {
            const int i = tid;
            const float e = ei[i];
            const __half2* cp2 = (const __half2*)&g_xBC[(size_t)(base + i) * CD + DI + NS + n0];
            __half2* mrow = (__half2*)(Mt + i * 40);
#pragma unroll
            for (int j2 = 0; j2 < 16; j2++) {
                __half2 v = cp2[j2];
                mrow[j2] = __floats2half2_rn(e * __low2float(v), e * __high2float(v));
            }
        }
        __syncthreads();
#pragma unroll
        for (int kk = 0; kk < 2; kk++) {
            uint32_t af[4][4];
#pragma unroll
            for (int mb = 0; mb < 4; mb++)
                LDSM4(af[mb], smem_u32(Mt + (wm + mb * 16 + fr) * 40 + kk * 16 + fch));
            uint32_t bf[2][4];
#pragma unroll
            for (int nb2 = 0; nb2 < 2; nb2++)
                LDSM4(bf[nb2], smem_u32(prevB + (wn + nb2 * 16 + fr) * 136 + n0 + kk * 16 + fch));
#pragma unroll
            for (int mb = 0; mb < 4; mb++)
#pragma unroll
                for (int nb = 0; nb < 4; nb++)
                    MMAF16(acc[mb][nb], af[mb], bf[nb >> 1][nb & 1], bf[nb >> 1][(nb & 1) + 2]);
        }
        __syncthreads();
    }

    // ---- epilogue ----
    const float dph = Dp[h];
    const int er = lane >> 2, ec = (lane & 3) * 2;
#pragma unroll
    for (int mb = 0; mb < 4; mb++) {
        int i0 = wm + mb * 16 + er;
#pragma unroll
        for (int nb = 0; nb < 4; nb++) {
            int p = wn + nb * 8 + ec;
            float x00 = __half2float(xT[(size_t)p * 264 + i0]);
            float x01 = __half2float(xT[(size_t)(p + 1) * 264 + i0]);
            float x10 = __half2float(xT[(size_t)p * 264 + i0 + 8]);
            float x11 = __half2float(xT[(size_t)(p + 1) * 264 + i0 + 8]);
            *(__half2*)&g_y[(size_t)(base + i0) * DI + h * 64 + p] =
                __halves2half2(__float2half_rn(acc[mb][nb][0] + dph * x00),
                               __float2half_rn(acc[mb][nb][1] + dph * x01));
            *(__half2*)&g_y[(size_t)(base + i0 + 8) * DI + h * 64 + p] =
                __halves2half2(__float2half_rn(acc[mb][nb][2] + dph * x10),
                               __float2half_rn(acc[mb][nb][3] + dph * x11));
        }
    }
}

// ---------------- gate (silu(z)) + RMSNorm; vectorized half2 ----------------
__global__ __launch_bounds__(256) void gate_norm_kernel(const float* __restrict__ norm_w)
{
    __shared__ float buf[DI];
    __shared__ float red[8];
    int r = blockIdx.x;
    int tid = threadIdx.x;
    const __half2* yrow = (const __half2*)&g_y[(size_t)r * DI];
    const __half2* zrow = (const __half2*)&g_zxh[(size_t)r * DPJA];
    float ss = 0.f;
#pragma unroll
    for (int e = 0; e < 8; e++) {
        int c2 = tid + e * 256;
        float2 y = __half22float2(yrow[c2]);
        float2 z = __half22float2(zrow[c2]);
        float g0 = y.x * (z.x / (1.f + __expf(-z.x)));
        float g1 = y.y * (z.y / (1.f + __expf(-z.y)));
        buf[2*c2]   = g0;
        buf[2*c2+1] = g1;
        ss += g0*g0 + g1*g1;
    }
#pragma unroll
    for (int o = 16; o > 0; o >>= 1) ss += __shfl_xor_sync(0xffffffffu, ss, o);
    if ((tid & 31) == 0) red[tid >> 5] = ss;
    __syncthreads();
    float tot = 0.f;
#pragma unroll
    for (int q = 0; q < 8; q++) tot += red[q];
    float scale = rsqrtf(tot / (float)DI + 1e-5f);
    __half2* orow = (__half2*)&g_yh[(size_t)r * DI];
#pragma unroll
    for (int e = 0; e < 8; e++) {
        int c2 = tid + e * 256;
        float g0 = buf[2*c2]   * scale * norm_w[2*c2];
        float g1 = buf[2*c2+1] * scale * norm_w[2*c2+1];
        orow[c2] = __floats2half2_rn(g0, g1);
    }
}

// ---------------- launch ----------------
extern "C" void kernel_launch(void* const* d_in, const int* in_sizes, int n_in,
                              void* d_out, int out_size)
{
    const float* u       = (const float*)d_in[0];
    const float* W_in    = (const float*)d_in[1];
    const float* conv_w  = (const float*)d_in[2];
    const float* conv_b  = (const float*)d_in[3];
    const float* dt_bias = (const float*)d_in[4];
    const float* A_log   = (const float*)d_in[5];
    const float* Dp      = (const float*)d_in[6];
    const float* norm_w  = (const float*)d_in[7];
    const float* W_out   = (const float*)d_in[8];
    float* out = (float*)d_out;

    __half *zxh, *uh, *wi1, *yh, *wo1;
    cudaGetSymbolAddress((void**)&zxh, g_zxh);
    cudaGetSymbolAddress((void**)&uh,  g_uh);
    cudaGetSymbolAddress((void**)&wi1, g_wi1);
    cudaGetSymbolAddress((void**)&yh,  g_yh);
    cudaGetSymbolAddress((void**)&wo1, g_wo1);

    cudaFuncSetAttribute(gemm_f16<true>,  cudaFuncAttributeMaxDynamicSharedMemorySize, FGEMM_SMEM);
    cudaFuncSetAttribute(gemm_f16<false>, cudaFuncAttributeMaxDynamicSharedMemorySize, FGEMM_SMEM);
    cudaFuncSetAttribute(cbt_tc,    cudaFuncAttributeMaxDynamicSharedMemorySize, CBT_SMEM);
    cudaFuncSetAttribute(states_tc, cudaFuncAttributeMaxDynamicSharedMemorySize, ST_SMEM);
    cudaFuncSetAttribute(y_tc,      cudaFuncAttributeMaxDynamicSharedMemorySize, YTC_SMEM);

    // ONE side stream + events (R15-proven resource footprint)
    cudaStream_t s2;
    cudaStreamCreateWithFlags(&s2, cudaStreamNonBlocking);
    cudaEvent_t ev0, ev_wi, ev_wo, ev_g1, ev_dt, ev_conv, ev_cbt;
    cudaEventCreateWithFlags(&ev0,     cudaEventDisableTiming);
    cudaEventCreateWithFlags(&ev_wi,   cudaEventDisableTiming);
    cudaEventCreateWithFlags(&ev_wo,   cudaEventDisableTiming);
    cudaEventCreateWithFlags(&ev_g1,   cudaEventDisableTiming);
    cudaEventCreateWithFlags(&ev_dt,   cudaEventDisableTiming);
    cudaEventCreateWithFlags(&ev_conv, cudaEventDisableTiming);
    cudaEventCreateWithFlags(&ev_cbt,  cudaEventDisableTiming);

    // fork side stream from origin
    cudaEventRecord(ev0, 0);
    cudaStreamWaitEvent(s2, ev0, 0);

    // s2: convert W_in (concurrent with cvt_u on s0)
    {
        long n4 = (long)DPJA * DM / 4;
        cvt_h1_pad_kernel<<<(int)((n4 + 255) / 256), 256, 0, s2>>>(W_in, wi1, n4, DPJ, DM/4);
        cudaEventRecord(ev_wi, s2);
    }
    // s2: convert W_out (hidden under GEMM1; consumed only by final GEMM)
    {
        long n4 = (long)DM * DI / 4;
        cvt_h1_kernel<<<(int)((n4 + 255) / 256), 256, 0, s2>>>(W_out, wo1, n4);
        cudaEventRecord(ev_wo, s2);
    }

    // s0: convert u
    {
        long n4 = (long)RW * DM / 4;
        cvt_h1_kernel<<<(int)((n4 + 255) / 256), 256>>>(u, uh, n4);
    }
    cudaStreamWaitEvent(0, ev_wi, 0);

    // 1) in-proj (fp16 GEMM 128x128, fp16 output)
    gemm_f16<true><<<dim3(DPJA/128, RW/128), 256, FGEMM_SMEM>>>(uh, wi1, zxh, DM, DPJA);
    cudaEventRecord(ev_g1, 0);

    // s2: dt softplus + cumsum (depends only on GEMM1; overlaps conv)
    cudaStreamWaitEvent(s2, ev_g1, 0);
    dt_cumsum_kernel<<<dim3(NCH, NH), 256, 0, s2>>>(dt_bias, A_log);
    cudaEventRecord(ev_dt, s2);

    // 2) conv + silu (s0)
    conv_silu_kernel<<<dim3(CD/256, RW/CT_ROWS), 256>>>(conv_w, conv_b);
    cudaEventRecord(ev_conv, 0);

    // s2: per-chunk CBt (depends on conv; overlaps states/scan)
    cudaStreamWaitEvent(s2, ev_conv, 0);
    cbt_tc<<<dim3(2, NCH), 256, CBT_SMEM, s2>>>();
    cudaEventRecord(ev_cbt, s2);

    // s0: states (needs conv + dt)
    cudaStreamWaitEvent(0, ev_dt, 0);
    states_tc<<<dim3(NCH, NH), 256, ST_SMEM>>>();

    // s0: inter-chunk scan
    scan_kernel<<<2048, 256>>>();

    // s0: fused y (needs scan + cbt)
    cudaStreamWaitEvent(0, ev_cbt, 0);
    y_tc<<<dim3(NCH, NH), 256, YTC_SMEM>>>(Dp);

    // s0: gate + RMSNorm
    gate_norm_kernel<<<RW, 256>>>(norm_w);

    // s0: out-proj (needs gate_norm + W_out conversion)
    cudaStreamWaitEvent(0, ev_wo, 0);
    gemm_f16<false><<<dim3(DM/128, RW/128), 256, FGEMM_SMEM>>>(yh, wo1, out, DI, DM);
}